// round 2
// baseline (speedup 1.0000x reference)
#include <cuda_runtime.h>
#include <math_constants.h>
#include <cstdint>

#define BB 8
#define SS 4096
#define DD 512
#define MEM 256
#define HID 1024
#define KK 768           // MEM + DD
#define NF 8192          // 2*S FFT size

// ---------------- scratch (no allocations allowed) ----------------
__device__ float  g_u[BB * SS];                       // 128 KB
__device__ float2 g_Ufft[BB * NF];                    // 512 KB
__device__ float2 g_Hfft[MEM * NF];                   // 16 MB
__device__ float  g_feat[(size_t)BB * KK * SS];       // 100.7 MB: [b][k][s]; k<256 = m, k>=256 = x^T

// ---------------- u = relu(x @ Wu^T + b) ----------------
__global__ void k_u(const float* __restrict__ x, const float* __restrict__ w,
                    const float* __restrict__ b0) {
    int r = blockIdx.x;          // b*S + t
    int tid = threadIdx.x;       // 128 threads, one float4 each (512 floats)
    const float4* xv = reinterpret_cast<const float4*>(x) + (size_t)r * 128;
    const float4* wv = reinterpret_cast<const float4*>(w);
    float4 a = xv[tid], ww = wv[tid];
    float p = a.x * ww.x + a.y * ww.y + a.z * ww.z + a.w * ww.w;
    __shared__ float red[128];
    red[tid] = p;
    __syncthreads();
    if (tid < 64) red[tid] += red[tid + 64];
    __syncthreads();
    if (tid < 32) {
        float v = red[tid] + red[tid + 32];
        #pragma unroll
        for (int o = 16; o; o >>= 1) v += __shfl_down_sync(0xffffffffu, v, o);
        if (tid == 0) g_u[r] = fmaxf(v + b0[0], 0.f);
    }
}

// ---------------- forward FFT: DIF radix-2, natural in -> bit-reversed out ----------------
// input: real sequence of length SS, zero-padded to NF
__global__ void k_fft_fwd(const float* __restrict__ in, float2* __restrict__ out) {
    extern __shared__ float2 X[];
    int tid = threadIdx.x;
    const float* src = in + (size_t)blockIdx.x * SS;
    for (int j = tid; j < NF; j += 512)
        X[j] = make_float2(j < SS ? src[j] : 0.f, 0.f);
    __syncthreads();
    for (int m = NF >> 1; m >= 1; m >>= 1) {
        float fm = (float)m;
        for (int t = tid; t < (NF >> 1); t += 512) {
            int j = t & (m - 1);
            int i0 = 2 * t - j, i1 = i0 + m;
            float2 a = X[i0], b = X[i1];
            float sn, cs;
            __sincosf(-CUDART_PI_F * (float)j / fm, &sn, &cs);
            X[i0] = make_float2(a.x + b.x, a.y + b.y);
            float dx = a.x - b.x, dy = a.y - b.y;
            X[i1] = make_float2(dx * cs - dy * sn, dx * sn + dy * cs);
        }
        __syncthreads();
    }
    float2* dst = out + (size_t)blockIdx.x * NF;
    for (int j = tid; j < NF; j += 512) dst[j] = X[j];
}

// ---------------- pointwise product + inverse FFT (DIT, bitrev in -> natural out) ----------------
__global__ void k_conv() {
    extern __shared__ float2 X[];
    int tid = threadIdx.x;
    int k = blockIdx.x, b = blockIdx.y;
    const float2* U  = g_Ufft + (size_t)b * NF;
    const float2* Hf = g_Hfft + (size_t)k * NF;
    for (int j = tid; j < NF; j += 512) {
        float2 u = U[j], h = Hf[j];
        X[j] = make_float2(u.x * h.x - u.y * h.y, u.x * h.y + u.y * h.x);
    }
    __syncthreads();
    for (int m = 1; m <= (NF >> 1); m <<= 1) {
        float fm = (float)m;
        for (int t = tid; t < (NF >> 1); t += 512) {
            int j = t & (m - 1);
            int i0 = 2 * t - j, i1 = i0 + m;
            float sn, cs;
            __sincosf(CUDART_PI_F * (float)j / fm, &sn, &cs);
            float2 a = X[i0], bb = X[i1];
            float bx = bb.x * cs - bb.y * sn;
            float by = bb.x * sn + bb.y * cs;
            X[i0] = make_float2(a.x + bx, a.y + by);
            X[i1] = make_float2(a.x - bx, a.y - by);
        }
        __syncthreads();
    }
    float* dst = g_feat + ((size_t)b * KK + k) * SS;
    const float inv = 1.f / NF;
    for (int s = tid; s < SS; s += 512) dst[s] = X[s].x * inv;
}

// ---------------- transpose x into feature buffer: feat[b][256+d][s] = x[b][s][d] ----------------
__global__ void k_xT(const float* __restrict__ x) {
    __shared__ float tile[32][33];
    int b = blockIdx.z;
    int s0 = blockIdx.x * 32, d0 = blockIdx.y * 32;
    int tx = threadIdx.x, ty = threadIdx.y;
    for (int i = ty; i < 32; i += 8)
        tile[i][tx] = x[((size_t)b * SS + s0 + i) * DD + d0 + tx];
    __syncthreads();
    for (int i = ty; i < 32; i += 8)
        g_feat[((size_t)b * KK + MEM + d0 + i) * SS + s0 + tx] = tile[tx][i];
}

// ---------------- packed f32x2 FMA ----------------
__device__ __forceinline__ float2 ffma2(float2 a, float2 b, float2 c) {
    unsigned long long A = *reinterpret_cast<unsigned long long*>(&a);
    unsigned long long Bv = *reinterpret_cast<unsigned long long*>(&b);
    unsigned long long C = *reinterpret_cast<unsigned long long*>(&c);
    unsigned long long R;
    asm("fma.rn.f32x2 %0, %1, %2, %3;" : "=l"(R) : "l"(A), "l"(Bv), "l"(C));
    return *reinterpret_cast<float2*>(&R);
}

// ---------------- h = relu(feat^T @ Wh^T + bias) ----------------
// C tile 128(s) x 128(h), BK=16, 256 threads, microtile 8s x 8h (s packed in pairs)
__global__ __launch_bounds__(256, 2) void k_gemm(const float* __restrict__ W,
                                                 const float* __restrict__ bias,
                                                 float* __restrict__ out) {
    __shared__ __align__(16) float2 As[16][64];    // [k][s-pair]      8 KB
    __shared__ float2 Bs[16][128];                 // [k][h], dup'd   16 KB
    int tid = threadIdx.x;
    int s0 = blockIdx.x * 128;
    int h0 = blockIdx.y * 128;
    int b  = blockIdx.z;
    int tx = tid & 15, ty = tid >> 4;

    const float* featb = g_feat + (size_t)b * KK * SS;

    float2 acc[4][8];
    #pragma unroll
    for (int i = 0; i < 4; i++)
        #pragma unroll
        for (int q = 0; q < 8; q++) acc[i][q] = make_float2(0.f, 0.f);

    int la  = tid & 63;        // s-pair index for A loads
    int lk  = tid >> 6;        // 0..3
    int lh  = tid >> 1;        // 0..127 for B loads
    int lq8 = (tid & 1) * 8;

    for (int k0 = 0; k0 < KK; k0 += 16) {
        #pragma unroll
        for (int q = 0; q < 4; q++) {
            int kk = lk * 4 + q;
            As[kk][la] = *reinterpret_cast<const float2*>(
                featb + (size_t)(k0 + kk) * SS + s0 + 2 * la);
        }
        const float* wp = W + (size_t)(h0 + lh) * KK + k0 + lq8;
        float4 w0 = *reinterpret_cast<const float4*>(wp);
        float4 w1 = *reinterpret_cast<const float4*>(wp + 4);
        Bs[lq8 + 0][lh] = make_float2(w0.x, w0.x);
        Bs[lq8 + 1][lh] = make_float2(w0.y, w0.y);
        Bs[lq8 + 2][lh] = make_float2(w0.z, w0.z);
        Bs[lq8 + 3][lh] = make_float2(w0.w, w0.w);
        Bs[lq8 + 4][lh] = make_float2(w1.x, w1.x);
        Bs[lq8 + 5][lh] = make_float2(w1.y, w1.y);
        Bs[lq8 + 6][lh] = make_float2(w1.z, w1.z);
        Bs[lq8 + 7][lh] = make_float2(w1.w, w1.w);
        __syncthreads();
        #pragma unroll
        for (int kk = 0; kk < 16; kk++) {
            float2 a[4];
            *reinterpret_cast<float4*>(&a[0]) = *reinterpret_cast<float4*>(&As[kk][ty * 4]);
            *reinterpret_cast<float4*>(&a[2]) = *reinterpret_cast<float4*>(&As[kk][ty * 4 + 2]);
            float2 bb[8];
            #pragma unroll
            for (int q = 0; q < 8; q++) bb[q] = Bs[kk][tx + 16 * q];
            #pragma unroll
            for (int sp = 0; sp < 4; sp++)
                #pragma unroll
                for (int q = 0; q < 8; q++)
                    acc[sp][q] = ffma2(a[sp], bb[q], acc[sp][q]);
        }
        __syncthreads();
    }

    #pragma unroll
    for (int q = 0; q < 8; q++) {
        int h = h0 + tx + 16 * q;
        float bv = bias[h];
        #pragma unroll
        for (int sp = 0; sp < 4; sp++) {
            int s = s0 + ty * 8 + sp * 2;
            size_t base = ((size_t)(b * SS + s)) * HID + h;
            out[base]       = fmaxf(acc[sp][q].x + bv, 0.f);
            out[base + HID] = fmaxf(acc[sp][q].y + bv, 0.f);
        }
    }
}

// ---------------- tail: second output = h[:, -1, :] ----------------
__global__ void k_tail(float* __restrict__ out) {
    int b = blockIdx.x, h = threadIdx.x;
    out[(size_t)BB * SS * HID + (size_t)b * HID + h] =
        out[((size_t)b * SS + (SS - 1)) * HID + h];
}

// ---------------- launch ----------------
extern "C" void kernel_launch(void* const* d_in, const int* in_sizes, int n_in,
                              void* d_out, int out_size) {
    const float* x  = (const float*)d_in[0];   // (8, 4096, 512)
    const float* Wu = (const float*)d_in[1];   // (1, 512)
    const float* bu = (const float*)d_in[2];   // (1,)
    const float* Wh = (const float*)d_in[3];   // (1024, 768)
    const float* bh = (const float*)d_in[4];   // (1024,)
    const float* H  = (const float*)d_in[5];   // (256, 4096)
    float* out = (float*)d_out;

    cudaFuncSetAttribute(k_fft_fwd, cudaFuncAttributeMaxDynamicSharedMemorySize, NF * 8);
    cudaFuncSetAttribute(k_conv,    cudaFuncAttributeMaxDynamicSharedMemorySize, NF * 8);

    void *pu, *puf, *phf;
    cudaGetSymbolAddress(&pu,  g_u);
    cudaGetSymbolAddress(&puf, g_Ufft);
    cudaGetSymbolAddress(&phf, g_Hfft);

    k_u<<<BB * SS, 128>>>(x, Wu, bu);
    k_fft_fwd<<<BB, 512, NF * 8>>>((const float*)pu, (float2*)puf);
    k_fft_fwd<<<MEM, 512, NF * 8>>>(H, (float2*)phf);
    k_xT<<<dim3(SS / 32, DD / 32, BB), dim3(32, 8)>>>(x);
    k_conv<<<dim3(MEM, BB), 512, NF * 8>>>();
    k_gemm<<<dim3(SS / 128, HID / 128, BB), 256>>>(Wh, bh, out);
    k_tail<<<BB, HID>>>(out);
}

// round 4
// speedup vs baseline: 2.2943x; 2.2943x over previous
#include <cuda_runtime.h>
#include <cuda_fp16.h>
#include <math_constants.h>
#include <cstdint>

#define BB 8
#define SS 4096
#define DD 512
#define MEM 256
#define HID 1024
#define KK 768
#define NF 8192
#define NH 4096          // NF/2

// ---------------- device scratch ----------------
__device__ float  g_u[BB * SS];
__device__ float2 g_Ufft[BB * NF];
__device__ float2 g_Hfft[MEM * NF];
__device__ float2 g_tw[NH];
__device__ float  g_m[(size_t)BB * MEM * SS];
__device__ half   g_featH[(size_t)BB * SS * KK];   // [b][s][k] fp16, 50 MB
__device__ half   g_W16[(size_t)HID * KK];         // [h][k] fp16

__device__ __forceinline__ uint32_t s2u(const void* p) {
    uint32_t a;
    asm("{ .reg .u64 t; cvta.to.shared.u64 t, %1; cvt.u32.u64 %0, t; }" : "=r"(a) : "l"(p));
    return a;
}

// ---------------- twiddle table: g_tw[r] = exp(-i*pi*r/NH) ----------------
__global__ void k_tw() {
    int r = blockIdx.x * 256 + threadIdx.x;
    float s, c;
    sincosf(-CUDART_PI_F * (float)r / (float)NH, &s, &c);
    g_tw[r] = make_float2(c, s);
}

// ---------------- u = relu(x @ Wu^T + b) ----------------
__global__ void k_u(const float* __restrict__ x, const float* __restrict__ w,
                    const float* __restrict__ b0) {
    int r = blockIdx.x;
    int tid = threadIdx.x;
    const float4* xv = reinterpret_cast<const float4*>(x) + (size_t)r * 128;
    const float4* wv = reinterpret_cast<const float4*>(w);
    float4 a = xv[tid], ww = wv[tid];
    float p = a.x * ww.x + a.y * ww.y + a.z * ww.z + a.w * ww.w;
    __shared__ float red[128];
    red[tid] = p;
    __syncthreads();
    if (tid < 64) red[tid] += red[tid + 64];
    __syncthreads();
    if (tid < 32) {
        float v = red[tid] + red[tid + 32];
        #pragma unroll
        for (int o = 16; o; o >>= 1) v += __shfl_down_sync(0xffffffffu, v, o);
        if (tid == 0) g_u[r] = fmaxf(v + b0[0], 0.f);
    }
}

// ---------------- forward FFT: DIF radix-2, natural in -> bit-reversed out ----------------
__global__ void k_fft_fwd(const float* __restrict__ in, float2* __restrict__ out) {
    extern __shared__ float2 X[];
    int tid = threadIdx.x;
    const float* src = in + (size_t)blockIdx.x * SS;
    for (int j = tid; j < NF; j += 512)
        X[j] = make_float2(j < SS ? src[j] : 0.f, 0.f);
    __syncthreads();
    for (int m = NH, stride = 1; m >= 1; m >>= 1, stride <<= 1) {
        for (int t = tid; t < NH; t += 512) {
            int j = t & (m - 1);
            int i0 = 2 * t - j, i1 = i0 + m;
            float2 a = X[i0], b = X[i1];
            float2 w = g_tw[j * stride];
            X[i0] = make_float2(a.x + b.x, a.y + b.y);
            float dx = a.x - b.x, dy = a.y - b.y;
            X[i1] = make_float2(dx * w.x - dy * w.y, dx * w.y + dy * w.x);
        }
        __syncthreads();
    }
    float2* dst = out + (size_t)blockIdx.x * NF;
    for (int j = tid; j < NF; j += 512) dst[j] = X[j];
}

// ---------------- pointwise product + inverse FFT (DIT, bitrev in -> natural) ----------------
__global__ void k_conv() {
    extern __shared__ float2 X[];
    int tid = threadIdx.x;
    int k = blockIdx.x, b = blockIdx.y;
    const float2* U  = g_Ufft + (size_t)b * NF;
    const float2* Hf = g_Hfft + (size_t)k * NF;
    for (int j = tid; j < NF; j += 512) {
        float2 u = U[j], h = Hf[j];
        X[j] = make_float2(u.x * h.x - u.y * h.y, u.x * h.y + u.y * h.x);
    }
    __syncthreads();
    for (int m = 1, stride = NH; m <= NH; m <<= 1, stride >>= 1) {
        for (int t = tid; t < NH; t += 512) {
            int j = t & (m - 1);
            int i0 = 2 * t - j, i1 = i0 + m;
            float2 w = g_tw[j * stride];          // inverse: conjugate
            float cs = w.x, sn = -w.y;
            float2 a = X[i0], bb = X[i1];
            float bx = bb.x * cs - bb.y * sn;
            float by = bb.x * sn + bb.y * cs;
            X[i0] = make_float2(a.x + bx, a.y + by);
            X[i1] = make_float2(a.x - bx, a.y - by);
        }
        __syncthreads();
    }
    float* dst = g_m + ((size_t)b * MEM + k) * SS;
    const float inv = 1.f / NF;
    for (int s = tid; s < SS; s += 512) dst[s] = X[s].x * inv;
}

// ---------------- m [b][k][s] fp32 -> featH [b][s][k] fp16 (k<256) ----------------
__global__ void k_mc() {
    __shared__ float tile[32][33];
    int b = blockIdx.z;
    int s0 = blockIdx.x * 32, k0 = blockIdx.y * 32;
    int tx = threadIdx.x, ty = threadIdx.y;
    for (int i = ty; i < 32; i += 8)
        tile[i][tx] = g_m[((size_t)b * MEM + k0 + i) * SS + s0 + tx];
    __syncthreads();
    for (int i = ty; i < 32; i += 8)
        g_featH[((size_t)b * SS + s0 + i) * KK + k0 + tx] = __float2half_rn(tile[tx][i]);
}

// ---------------- x [b][s][d] -> featH [b][s][256+d] fp16 ----------------
__global__ void k_xc(const float* __restrict__ x) {
    size_t r = blockIdx.x;                 // b*S + s
    int t = threadIdx.x;                   // 64 threads, 8 elems each
    const float4* src = reinterpret_cast<const float4*>(x + r * DD) + t * 2;
    float4 v0 = src[0], v1 = src[1];
    half2 h[4];
    h[0] = __floats2half2_rn(v0.x, v0.y);
    h[1] = __floats2half2_rn(v0.z, v0.w);
    h[2] = __floats2half2_rn(v1.x, v1.y);
    h[3] = __floats2half2_rn(v1.z, v1.w);
    *reinterpret_cast<uint4*>(g_featH + r * KK + MEM + t * 8) = *reinterpret_cast<uint4*>(h);
}

// ---------------- W fp32 -> fp16 ----------------
__global__ void k_w16(const float* __restrict__ W) {
    size_t i = ((size_t)blockIdx.x * 128 + threadIdx.x) * 8;
    const float4* src = reinterpret_cast<const float4*>(W + i);
    float4 v0 = src[0], v1 = src[1];
    half2 h[4];
    h[0] = __floats2half2_rn(v0.x, v0.y);
    h[1] = __floats2half2_rn(v0.z, v0.w);
    h[2] = __floats2half2_rn(v1.x, v1.y);
    h[3] = __floats2half2_rn(v1.z, v1.w);
    *reinterpret_cast<uint4*>(g_W16 + i) = *reinterpret_cast<uint4*>(h);
}

// ---------------- HMMA GEMM: out[b][s][h] = relu(featH . W16^T + bias) ----------------
// CTA 128(s) x 128(h), 8 warps (4m x 2n), warp 32x64, BK=32, double-buffered cp.async
#define PAD 40
__global__ __launch_bounds__(256) void k_gemm(const float* __restrict__ bias,
                                              float* __restrict__ out) {
    __shared__ __align__(16) half As[2][128][PAD];
    __shared__ __align__(16) half Bs[2][128][PAD];
    int tid = threadIdx.x;
    int lane = tid & 31, warp = tid >> 5;
    int wm = warp & 3, wn = warp >> 2;
    int s0 = blockIdx.x * 128, h0 = blockIdx.y * 128, b = blockIdx.z;

    const half* Ag = g_featH + ((size_t)b * SS + s0) * KK;
    const half* Bg = g_W16 + (size_t)h0 * KK;
    uint32_t sA = s2u(As), sB = s2u(Bs);

    float acc[2][8][4];
    #pragma unroll
    for (int mi = 0; mi < 2; mi++)
        #pragma unroll
        for (int ni = 0; ni < 8; ni++)
            #pragma unroll
            for (int q = 0; q < 4; q++) acc[mi][ni][q] = 0.f;

    auto load = [&](int kt, int buf) {
        int k0 = kt * 32;
        #pragma unroll
        for (int j = 0; j < 2; j++) {
            int idx = tid + j * 256;
            int row = idx >> 2, cc = idx & 3;
            uint32_t off = ((uint32_t)(buf * 128 + row) * PAD + cc * 8) * 2;
            const half* pa = Ag + (size_t)row * KK + k0 + cc * 8;
            const half* pb = Bg + (size_t)row * KK + k0 + cc * 8;
            asm volatile("cp.async.ca.shared.global [%0], [%1], 16;" :: "r"(sA + off), "l"(pa));
            asm volatile("cp.async.ca.shared.global [%0], [%1], 16;" :: "r"(sB + off), "l"(pb));
        }
        asm volatile("cp.async.commit_group;");
    };

    load(0, 0);
    int arow = lane & 15;
    int acol = (lane >> 4) << 3;
    int brow = ((lane >> 4) << 3) + (lane & 7);
    int bcol = lane & 8;

    for (int kt = 0; kt < KK / 32; kt++) {
        int buf = kt & 1;
        if (kt + 1 < KK / 32) {
            load(kt + 1, buf ^ 1);
            asm volatile("cp.async.wait_group 1;");
        } else {
            asm volatile("cp.async.wait_group 0;");
        }
        __syncthreads();
        #pragma unroll
        for (int ks = 0; ks < 32; ks += 16) {
            uint32_t am[2][4];
            #pragma unroll
            for (int mi = 0; mi < 2; mi++) {
                uint32_t a = sA + ((uint32_t)(buf * 128 + wm * 32 + mi * 16 + arow) * PAD
                                   + ks + acol) * 2;
                asm volatile("ldmatrix.sync.aligned.m8n8.x4.shared.b16 {%0,%1,%2,%3}, [%4];"
                             : "=r"(am[mi][0]), "=r"(am[mi][1]), "=r"(am[mi][2]), "=r"(am[mi][3])
                             : "r"(a));
            }
            uint32_t bm[4][4];
            #pragma unroll
            for (int p = 0; p < 4; p++) {
                uint32_t a = sB + ((uint32_t)(buf * 128 + wn * 64 + p * 16 + brow) * PAD
                                   + ks + bcol) * 2;
                asm volatile("ldmatrix.sync.aligned.m8n8.x4.shared.b16 {%0,%1,%2,%3}, [%4];"
                             : "=r"(bm[p][0]), "=r"(bm[p][1]), "=r"(bm[p][2]), "=r"(bm[p][3])
                             : "r"(a));
            }
            #pragma unroll
            for (int mi = 0; mi < 2; mi++)
                #pragma unroll
                for (int p = 0; p < 4; p++) {
                    asm volatile(
                        "mma.sync.aligned.m16n8k16.row.col.f32.f16.f16.f32 "
                        "{%0,%1,%2,%3}, {%4,%5,%6,%7}, {%8,%9}, {%0,%1,%2,%3};"
                        : "+f"(acc[mi][2*p][0]), "+f"(acc[mi][2*p][1]),
                          "+f"(acc[mi][2*p][2]), "+f"(acc[mi][2*p][3])
                        : "r"(am[mi][0]), "r"(am[mi][1]), "r"(am[mi][2]), "r"(am[mi][3]),
                          "r"(bm[p][0]), "r"(bm[p][1]));
                    asm volatile(
                        "mma.sync.aligned.m16n8k16.row.col.f32.f16.f16.f32 "
                        "{%0,%1,%2,%3}, {%4,%5,%6,%7}, {%8,%9}, {%0,%1,%2,%3};"
                        : "+f"(acc[mi][2*p+1][0]), "+f"(acc[mi][2*p+1][1]),
                          "+f"(acc[mi][2*p+1][2]), "+f"(acc[mi][2*p+1][3])
                        : "r"(am[mi][0]), "r"(am[mi][1]), "r"(am[mi][2]), "r"(am[mi][3]),
                          "r"(bm[p][2]), "r"(bm[p][3]));
                }
        }
        __syncthreads();
    }

    int r = lane >> 2, c = (lane & 3) * 2;
    #pragma unroll
    for (int mi = 0; mi < 2; mi++)
        #pragma unroll
        for (int ni = 0; ni < 8; ni++) {
            int h = h0 + wn * 64 + ni * 8 + c;
            int s = s0 + wm * 32 + mi * 16 + r;
            float b0v = bias[h], b1v = bias[h + 1];
            size_t o0 = ((size_t)b * SS + s) * HID + h;
            float2 v0 = make_float2(fmaxf(acc[mi][ni][0] + b0v, 0.f),
                                    fmaxf(acc[mi][ni][1] + b1v, 0.f));
            *reinterpret_cast<float2*>(out + o0) = v0;
            float2 v1 = make_float2(fmaxf(acc[mi][ni][2] + b0v, 0.f),
                                    fmaxf(acc[mi][ni][3] + b1v, 0.f));
            *reinterpret_cast<float2*>(out + o0 + 8 * HID) = v1;
        }
}

// ---------------- tail: second output = h[:, -1, :] ----------------
__global__ void k_tail(float* __restrict__ out) {
    int b = blockIdx.x, h = threadIdx.x;
    out[(size_t)BB * SS * HID + (size_t)b * HID + h] =
        out[((size_t)b * SS + (SS - 1)) * HID + h];
}

// ---------------- launch ----------------
extern "C" void kernel_launch(void* const* d_in, const int* in_sizes, int n_in,
                              void* d_out, int out_size) {
    const float* x  = (const float*)d_in[0];   // (8, 4096, 512)
    const float* Wu = (const float*)d_in[1];   // (1, 512)
    const float* bu = (const float*)d_in[2];   // (1,)
    const float* Wh = (const float*)d_in[3];   // (1024, 768)
    const float* bh = (const float*)d_in[4];   // (1024,)
    const float* H  = (const float*)d_in[5];   // (256, 4096)
    float* out = (float*)d_out;

    cudaFuncSetAttribute(k_fft_fwd, cudaFuncAttributeMaxDynamicSharedMemorySize, NF * 8);
    cudaFuncSetAttribute(k_conv,    cudaFuncAttributeMaxDynamicSharedMemorySize, NF * 8);

    void *pu, *puf, *phf;
    cudaGetSymbolAddress(&pu,  g_u);
    cudaGetSymbolAddress(&puf, g_Ufft);
    cudaGetSymbolAddress(&phf, g_Hfft);

    k_tw<<<NH / 256, 256>>>();
    k_u<<<BB * SS, 128>>>(x, Wu, bu);
    k_fft_fwd<<<BB, 512, NF * 8>>>((const float*)pu, (float2*)puf);
    k_fft_fwd<<<MEM, 512, NF * 8>>>(H, (float2*)phf);
    k_xc<<<BB * SS, 64>>>(x);
    k_w16<<<(HID * KK) / (128 * 8), 128>>>(Wh);
    k_conv<<<dim3(MEM, BB), 512, NF * 8>>>();
    k_mc<<<dim3(SS / 32, MEM / 32, BB), dim3(32, 8)>>>();
    k_gemm<<<dim3(SS / 128, HID / 128, BB), 256>>>(bh, out);
    k_tail<<<BB, HID>>>(out);
}

// round 5
// speedup vs baseline: 4.7204x; 2.0574x over previous
#include <cuda_runtime.h>
#include <cuda_fp16.h>
#include <math_constants.h>
#include <cstdint>

#define BB 8
#define SS 4096
#define DD 512
#define MEM 256
#define HID 1024
#define KK 768
#define NF 8192
#define NH 4096          // NF/2

// ---------------- device scratch ----------------
__device__ float  g_u[BB * SS];
__device__ float2 g_Ufft[BB * NF];
__device__ float2 g_Hfft[(MEM / 2) * NF];          // packed pair spectra, 8 MB
__device__ float2 g_tw[NH];
__device__ float  g_m[(size_t)BB * MEM * SS];
__device__ half   g_featH[(size_t)BB * SS * KK];   // [b][s][k] fp16, 50 MB
__device__ half   g_W16[(size_t)HID * KK];         // [h][k] fp16

__device__ __forceinline__ uint32_t s2u(const void* p) {
    uint32_t a;
    asm("{ .reg .u64 t; cvta.to.shared.u64 t, %1; cvt.u32.u64 %0, t; }" : "=r"(a) : "l"(p));
    return a;
}

// ---------------- twiddle table: g_tw[r] = exp(-i*pi*r/NH) ----------------
__global__ void k_tw() {
    int r = blockIdx.x * 256 + threadIdx.x;
    float s, c;
    sincosf(-CUDART_PI_F * (float)r / (float)NH, &s, &c);
    g_tw[r] = make_float2(c, s);
}

// ================= fused radix-2^2 FFT cores (512 threads, X[NF] in smem) =================
// Forward DIF: natural -> bit-reversed. 6 fused passes (m=4096..4) + final m=1 stage.
__device__ __forceinline__ void fft_fwd_core(float2* X, int tid) {
    #pragma unroll
    for (int p = 0; p < 6; p++) {
        const int m  = 4096 >> (2 * p);
        const int m2 = m >> 1;
        const int st = 4096 / m;
        const int st2 = st << 1;
        #pragma unroll
        for (int qq = 0; qq < 4; qq++) {
            int q = tid + qq * 512;
            int jj = q & (m2 - 1);
            int i = (q / m2) * 2 * m + jj;
            float2 a = X[i], b = X[i + m2], c = X[i + m], d = X[i + m + m2];
            float2 w1 = g_tw[jj * st];
            // stage m: (a,c) twiddle w1; (b,d) twiddle -i*w1
            float2 ap = make_float2(a.x + c.x, a.y + c.y);
            float2 cd = make_float2(a.x - c.x, a.y - c.y);
            float2 cp = make_float2(cd.x * w1.x - cd.y * w1.y, cd.x * w1.y + cd.y * w1.x);
            float2 bp = make_float2(b.x + d.x, b.y + d.y);
            float2 dd = make_float2(b.x - d.x, b.y - d.y);
            float2 dp = make_float2(dd.x * w1.y + dd.y * w1.x, dd.y * w1.y - dd.x * w1.x);
            // stage m2: twiddle w2 for both
            float2 w2 = g_tw[jj * st2];
            X[i] = make_float2(ap.x + bp.x, ap.y + bp.y);
            float2 e = make_float2(ap.x - bp.x, ap.y - bp.y);
            X[i + m2] = make_float2(e.x * w2.x - e.y * w2.y, e.x * w2.y + e.y * w2.x);
            X[i + m] = make_float2(cp.x + dp.x, cp.y + dp.y);
            float2 f = make_float2(cp.x - dp.x, cp.y - dp.y);
            X[i + m + m2] = make_float2(f.x * w2.x - f.y * w2.y, f.x * w2.y + f.y * w2.x);
        }
        __syncthreads();
    }
    // final stage m=1: twiddle-free
    #pragma unroll
    for (int qq = 0; qq < 8; qq++) {
        int t = tid + qq * 512;
        int i0 = 2 * t;
        float2 a = X[i0], b = X[i0 + 1];
        X[i0]     = make_float2(a.x + b.x, a.y + b.y);
        X[i0 + 1] = make_float2(a.x - b.x, a.y - b.y);
    }
    __syncthreads();
}

// Inverse DIT: bit-reversed -> natural (conjugate twiddles). 6 fused passes + final m=4096.
__device__ __forceinline__ void fft_inv_core(float2* X, int tid) {
    #pragma unroll
    for (int p = 0; p < 6; p++) {
        const int m  = 1 << (2 * p);
        const int st = 4096 / m;
        const int st2 = st >> 1;
        #pragma unroll
        for (int qq = 0; qq < 4; qq++) {
            int q = tid + qq * 512;
            int jj = q & (m - 1);
            int i = (q / m) * 4 * m + jj;
            float2 a = X[i], b = X[i + m], c = X[i + 2 * m], d = X[i + 3 * m];
            float2 w1 = g_tw[jj * st];
            float c1 = w1.x, s1 = -w1.y;         // conj
            float2 t1 = make_float2(b.x * c1 - b.y * s1, b.x * s1 + b.y * c1);
            float2 ap = make_float2(a.x + t1.x, a.y + t1.y);
            float2 bp = make_float2(a.x - t1.x, a.y - t1.y);
            float2 t2 = make_float2(d.x * c1 - d.y * s1, d.x * s1 + d.y * c1);
            float2 cp = make_float2(c.x + t2.x, c.y + t2.y);
            float2 dp = make_float2(c.x - t2.x, c.y - t2.y);
            float2 w2 = g_tw[jj * st2];
            float c2 = w2.x, s2 = -w2.y;         // conj
            float2 u1 = make_float2(cp.x * c2 - cp.y * s2, cp.x * s2 + cp.y * c2);
            X[i]         = make_float2(ap.x + u1.x, ap.y + u1.y);
            X[i + 2 * m] = make_float2(ap.x - u1.x, ap.y - u1.y);
            // second stage-2m twiddle = i * (c2 + i s2) = (-s2, c2)
            float2 u2 = make_float2(-dp.x * s2 - dp.y * c2, dp.x * c2 - dp.y * s2);
            X[i + m]     = make_float2(bp.x + u2.x, bp.y + u2.y);
            X[i + 3 * m] = make_float2(bp.x - u2.x, bp.y - u2.y);
        }
        __syncthreads();
    }
    // final stage m=4096
    #pragma unroll
    for (int qq = 0; qq < 8; qq++) {
        int t = tid + qq * 512;
        float2 a = X[t], b = X[t + 4096];
        float2 w = g_tw[t];
        float cs = w.x, sn = -w.y;
        float2 bb = make_float2(b.x * cs - b.y * sn, b.x * sn + b.y * cs);
        X[t]        = make_float2(a.x + bb.x, a.y + bb.y);
        X[t + 4096] = make_float2(a.x - bb.x, a.y - bb.y);
    }
    __syncthreads();
}

// ---------------- u = relu(x @ Wu^T + b) ----------------
__global__ void k_u(const float* __restrict__ x, const float* __restrict__ w,
                    const float* __restrict__ b0) {
    int r = blockIdx.x;
    int tid = threadIdx.x;
    const float4* xv = reinterpret_cast<const float4*>(x) + (size_t)r * 128;
    const float4* wv = reinterpret_cast<const float4*>(w);
    float4 a = xv[tid], ww = wv[tid];
    float p = a.x * ww.x + a.y * ww.y + a.z * ww.z + a.w * ww.w;
    __shared__ float red[128];
    red[tid] = p;
    __syncthreads();
    if (tid < 64) red[tid] += red[tid + 64];
    __syncthreads();
    if (tid < 32) {
        float v = red[tid] + red[tid + 32];
        #pragma unroll
        for (int o = 16; o; o >>= 1) v += __shfl_down_sync(0xffffffffu, v, o);
        if (tid == 0) g_u[r] = fmaxf(v + b0[0], 0.f);
    }
}

// ---------------- forward FFT of u rows (real, zero-padded) ----------------
__global__ void k_fft_fwd(const float* __restrict__ in, float2* __restrict__ out) {
    extern __shared__ float2 X[];
    int tid = threadIdx.x;
    const float* src = in + (size_t)blockIdx.x * SS;
    for (int j = tid; j < NF; j += 512)
        X[j] = make_float2(j < SS ? src[j] : 0.f, 0.f);
    __syncthreads();
    fft_fwd_core(X, tid);
    float2* dst = out + (size_t)blockIdx.x * NF;
    for (int j = tid; j < NF; j += 512) dst[j] = X[j];
}

// ---------------- forward FFT of packed H row pairs: (H[2k] + i*H[2k+1]) ----------------
__global__ void k_fft_fwdH(const float* __restrict__ H) {
    extern __shared__ float2 X[];
    int tid = threadIdx.x;
    int kp = blockIdx.x;
    const float* h1 = H + (size_t)(2 * kp) * SS;
    const float* h2 = H + (size_t)(2 * kp + 1) * SS;
    for (int j = tid; j < NF; j += 512)
        X[j] = (j < SS) ? make_float2(h1[j], h2[j]) : make_float2(0.f, 0.f);
    __syncthreads();
    fft_fwd_core(X, tid);
    float2* dst = g_Hfft + (size_t)kp * NF;
    for (int j = tid; j < NF; j += 512) dst[j] = X[j];
}

// ---------------- product + inverse FFT: two real conv rows per block ----------------
__global__ void k_conv() {
    extern __shared__ float2 X[];
    int tid = threadIdx.x;
    int kp = blockIdx.x, b = blockIdx.y;
    const float2* U  = g_Ufft + (size_t)b * NF;
    const float2* Hp = g_Hfft + (size_t)kp * NF;
    for (int j = tid; j < NF; j += 512) {
        float2 u = U[j], h = Hp[j];
        X[j] = make_float2(u.x * h.x - u.y * h.y, u.x * h.y + u.y * h.x);
    }
    __syncthreads();
    fft_inv_core(X, tid);
    float* d1 = g_m + ((size_t)b * MEM + 2 * kp) * SS;
    float* d2 = d1 + SS;
    const float inv = 1.f / NF;
    for (int s = tid; s < SS; s += 512) {
        float2 v = X[s];
        d1[s] = v.x * inv;
        d2[s] = v.y * inv;
    }
}

// ---------------- m [b][k][s] fp32 -> featH [b][s][k] fp16 (k<256) ----------------
__global__ void k_mc() {
    __shared__ float tile[32][33];
    int b = blockIdx.z;
    int s0 = blockIdx.x * 32, k0 = blockIdx.y * 32;
    int tx = threadIdx.x, ty = threadIdx.y;
    for (int i = ty; i < 32; i += 8)
        tile[i][tx] = g_m[((size_t)b * MEM + k0 + i) * SS + s0 + tx];
    __syncthreads();
    for (int i = ty; i < 32; i += 8)
        g_featH[((size_t)b * SS + s0 + i) * KK + k0 + tx] = __float2half_rn(tile[tx][i]);
}

// ---------------- x [b][s][d] -> featH [b][s][256+d] fp16 ----------------
__global__ void k_xc(const float* __restrict__ x) {
    size_t r = blockIdx.x;                 // b*S + s
    int t = threadIdx.x;                   // 64 threads, 8 elems each
    const float4* src = reinterpret_cast<const float4*>(x + r * DD) + t * 2;
    float4 v0 = src[0], v1 = src[1];
    half2 h[4];
    h[0] = __floats2half2_rn(v0.x, v0.y);
    h[1] = __floats2half2_rn(v0.z, v0.w);
    h[2] = __floats2half2_rn(v1.x, v1.y);
    h[3] = __floats2half2_rn(v1.z, v1.w);
    *reinterpret_cast<uint4*>(g_featH + r * KK + MEM + t * 8) = *reinterpret_cast<uint4*>(h);
}

// ---------------- W fp32 -> fp16 ----------------
__global__ void k_w16(const float* __restrict__ W) {
    size_t i = ((size_t)blockIdx.x * 128 + threadIdx.x) * 8;
    const float4* src = reinterpret_cast<const float4*>(W + i);
    float4 v0 = src[0], v1 = src[1];
    half2 h[4];
    h[0] = __floats2half2_rn(v0.x, v0.y);
    h[1] = __floats2half2_rn(v0.z, v0.w);
    h[2] = __floats2half2_rn(v1.x, v1.y);
    h[3] = __floats2half2_rn(v1.z, v1.w);
    *reinterpret_cast<uint4*>(g_W16 + i) = *reinterpret_cast<uint4*>(h);
}

// ---------------- HMMA GEMM: out[b][s][h] = relu(featH . W16^T + bias) ----------------
#define PAD 40
__global__ __launch_bounds__(256) void k_gemm(const float* __restrict__ bias,
                                              float* __restrict__ out) {
    __shared__ __align__(16) half As[2][128][PAD];
    __shared__ __align__(16) half Bs[2][128][PAD];
    int tid = threadIdx.x;
    int lane = tid & 31, warp = tid >> 5;
    int wm = warp & 3, wn = warp >> 2;
    int s0 = blockIdx.x * 128, h0 = blockIdx.y * 128, b = blockIdx.z;

    const half* Ag = g_featH + ((size_t)b * SS + s0) * KK;
    const half* Bg = g_W16 + (size_t)h0 * KK;
    uint32_t sA = s2u(As), sB = s2u(Bs);

    float acc[2][8][4];
    #pragma unroll
    for (int mi = 0; mi < 2; mi++)
        #pragma unroll
        for (int ni = 0; ni < 8; ni++)
            #pragma unroll
            for (int q = 0; q < 4; q++) acc[mi][ni][q] = 0.f;

    auto load = [&](int kt, int buf) {
        int k0 = kt * 32;
        #pragma unroll
        for (int j = 0; j < 2; j++) {
            int idx = tid + j * 256;
            int row = idx >> 2, cc = idx & 3;
            uint32_t off = ((uint32_t)(buf * 128 + row) * PAD + cc * 8) * 2;
            const half* pa = Ag + (size_t)row * KK + k0 + cc * 8;
            const half* pb = Bg + (size_t)row * KK + k0 + cc * 8;
            asm volatile("cp.async.ca.shared.global [%0], [%1], 16;" :: "r"(sA + off), "l"(pa));
            asm volatile("cp.async.ca.shared.global [%0], [%1], 16;" :: "r"(sB + off), "l"(pb));
        }
        asm volatile("cp.async.commit_group;");
    };

    load(0, 0);
    int arow = lane & 15;
    int acol = (lane >> 4) << 3;
    int brow = ((lane >> 4) << 3) + (lane & 7);
    int bcol = lane & 8;

    for (int kt = 0; kt < KK / 32; kt++) {
        int buf = kt & 1;
        if (kt + 1 < KK / 32) {
            load(kt + 1, buf ^ 1);
            asm volatile("cp.async.wait_group 1;");
        } else {
            asm volatile("cp.async.wait_group 0;");
        }
        __syncthreads();
        #pragma unroll
        for (int ks = 0; ks < 32; ks += 16) {
            uint32_t am[2][4];
            #pragma unroll
            for (int mi = 0; mi < 2; mi++) {
                uint32_t a = sA + ((uint32_t)(buf * 128 + wm * 32 + mi * 16 + arow) * PAD
                                   + ks + acol) * 2;
                asm volatile("ldmatrix.sync.aligned.m8n8.x4.shared.b16 {%0,%1,%2,%3}, [%4];"
                             : "=r"(am[mi][0]), "=r"(am[mi][1]), "=r"(am[mi][2]), "=r"(am[mi][3])
                             : "r"(a));
            }
            uint32_t bm[4][4];
            #pragma unroll
            for (int p = 0; p < 4; p++) {
                uint32_t a = sB + ((uint32_t)(buf * 128 + wn * 64 + p * 16 + brow) * PAD
                                   + ks + bcol) * 2;
                asm volatile("ldmatrix.sync.aligned.m8n8.x4.shared.b16 {%0,%1,%2,%3}, [%4];"
                             : "=r"(bm[p][0]), "=r"(bm[p][1]), "=r"(bm[p][2]), "=r"(bm[p][3])
                             : "r"(a));
            }
            #pragma unroll
            for (int mi = 0; mi < 2; mi++)
                #pragma unroll
                for (int p = 0; p < 4; p++) {
                    asm volatile(
                        "mma.sync.aligned.m16n8k16.row.col.f32.f16.f16.f32 "
                        "{%0,%1,%2,%3}, {%4,%5,%6,%7}, {%8,%9}, {%0,%1,%2,%3};"
                        : "+f"(acc[mi][2*p][0]), "+f"(acc[mi][2*p][1]),
                          "+f"(acc[mi][2*p][2]), "+f"(acc[mi][2*p][3])
                        : "r"(am[mi][0]), "r"(am[mi][1]), "r"(am[mi][2]), "r"(am[mi][3]),
                          "r"(bm[p][0]), "r"(bm[p][1]));
                    asm volatile(
                        "mma.sync.aligned.m16n8k16.row.col.f32.f16.f16.f32 "
                        "{%0,%1,%2,%3}, {%4,%5,%6,%7}, {%8,%9}, {%0,%1,%2,%3};"
                        : "+f"(acc[mi][2*p+1][0]), "+f"(acc[mi][2*p+1][1]),
                          "+f"(acc[mi][2*p+1][2]), "+f"(acc[mi][2*p+1][3])
                        : "r"(am[mi][0]), "r"(am[mi][1]), "r"(am[mi][2]), "r"(am[mi][3]),
                          "r"(bm[p][2]), "r"(bm[p][3]));
                }
        }
        __syncthreads();
    }

    int r = lane >> 2, c = (lane & 3) * 2;
    #pragma unroll
    for (int mi = 0; mi < 2; mi++)
        #pragma unroll
        for (int ni = 0; ni < 8; ni++) {
            int h = h0 + wn * 64 + ni * 8 + c;
            int s = s0 + wm * 32 + mi * 16 + r;
            float b0v = bias[h], b1v = bias[h + 1];
            size_t o0 = ((size_t)b * SS + s) * HID + h;
            float2 v0 = make_float2(fmaxf(acc[mi][ni][0] + b0v, 0.f),
                                    fmaxf(acc[mi][ni][1] + b1v, 0.f));
            *reinterpret_cast<float2*>(out + o0) = v0;
            float2 v1 = make_float2(fmaxf(acc[mi][ni][2] + b0v, 0.f),
                                    fmaxf(acc[mi][ni][3] + b1v, 0.f));
            *reinterpret_cast<float2*>(out + o0 + 8 * HID) = v1;
        }
}

// ---------------- tail: second output = h[:, -1, :] ----------------
__global__ void k_tail(float* __restrict__ out) {
    int b = blockIdx.x, h = threadIdx.x;
    out[(size_t)BB * SS * HID + (size_t)b * HID + h] =
        out[((size_t)b * SS + (SS - 1)) * HID + h];
}

// ---------------- launch ----------------
extern "C" void kernel_launch(void* const* d_in, const int* in_sizes, int n_in,
                              void* d_out, int out_size) {
    const float* x  = (const float*)d_in[0];   // (8, 4096, 512)
    const float* Wu = (const float*)d_in[1];   // (1, 512)
    const float* bu = (const float*)d_in[2];   // (1,)
    const float* Wh = (const float*)d_in[3];   // (1024, 768)
    const float* bh = (const float*)d_in[4];   // (1024,)
    const float* H  = (const float*)d_in[5];   // (256, 4096)
    float* out = (float*)d_out;

    cudaFuncSetAttribute(k_fft_fwd,  cudaFuncAttributeMaxDynamicSharedMemorySize, NF * 8);
    cudaFuncSetAttribute(k_fft_fwdH, cudaFuncAttributeMaxDynamicSharedMemorySize, NF * 8);
    cudaFuncSetAttribute(k_conv,     cudaFuncAttributeMaxDynamicSharedMemorySize, NF * 8);

    void *pu, *puf;
    cudaGetSymbolAddress(&pu,  g_u);
    cudaGetSymbolAddress(&puf, g_Ufft);

    k_tw<<<NH / 256, 256>>>();
    k_u<<<BB * SS, 128>>>(x, Wu, bu);
    k_fft_fwd<<<BB, 512, NF * 8>>>((const float*)pu, (float2*)puf);
    k_fft_fwdH<<<MEM / 2, 512, NF * 8>>>(H);
    k_xc<<<BB * SS, 64>>>(x);
    k_w16<<<(HID * KK) / (128 * 8), 128>>>(Wh);
    k_conv<<<dim3(MEM / 2, BB), 512, NF * 8>>>();
    k_mc<<<dim3(SS / 32, MEM / 32, BB), dim3(32, 8)>>>();
    k_gemm<<<dim3(SS / 128, HID / 128, BB), 256>>>(bh, out);
    k_tail<<<BB, HID>>>(out);
}